// round 2
// baseline (speedup 1.0000x reference)
#include <cuda_runtime.h>

#define NN 512      // tokens
#define DN 256      // d_node
#define DE 128      // d_edge
#define DH 32       // d_head
#define LN_EPS 1e-5f

#define NGROUPS 74          // outk: n-range groups (296 blocks = 74 groups x 4 m-tiles)

// Scratch (device globals: no allocation allowed)
__device__ float g_left[NN * DH];
__device__ float g_right[NN * DH];
__device__ float g_T[NN * DH * DE];   // [n][j][e] = [512][32][128]

// ---------------- packed f32x2 helpers (sm_103a) ----------------
__device__ __forceinline__ unsigned long long pk2(float lo, float hi) {
    unsigned long long r;
    asm("mov.b64 %0, {%1, %2};" : "=l"(r) : "f"(lo), "f"(hi));
    return r;
}
__device__ __forceinline__ void fma2(unsigned long long& d,
                                     unsigned long long a,
                                     unsigned long long b) {
    asm("fma.rn.f32x2 %0, %1, %2, %0;" : "+l"(d) : "l"(a), "l"(b));
}
__device__ __forceinline__ void upk2(unsigned long long v, float& lo, float& hi) {
    asm("mov.b64 {%0, %1}, %2;" : "=f"(lo), "=f"(hi) : "l"(v));
}

// ---------------- cp.async helpers ----------------
__device__ __forceinline__ void cp_async16(unsigned smem_addr, const void* gptr) {
    asm volatile("cp.async.cg.shared.global [%0], [%1], 16;"
                 :: "r"(smem_addr), "l"(gptr));
}
__device__ __forceinline__ void cp_commit() {
    asm volatile("cp.async.commit_group;");
}
template <int N>
__device__ __forceinline__ void cp_wait() {
    asm volatile("cp.async.wait_group %0;" :: "n"(N));
}

// ---------------- P1: LayerNorm + left/right projections ----------------
// Warp-per-token: no block syncs, shuffle-only reductions.
// grid 128 x 128 threads (4 warps = 4 tokens per block).
__global__ void p1_kernel(const float* __restrict__ node,
                          const float* __restrict__ ln_w,
                          const float* __restrict__ ln_b,
                          const float* __restrict__ wl,
                          const float* __restrict__ bl,
                          const float* __restrict__ wr,
                          const float* __restrict__ br) {
    __shared__ float xs[4][DN];

    int warp = threadIdx.x >> 5;
    int lane = threadIdx.x & 31;
    int n = blockIdx.x * 4 + warp;

    const float* np = node + n * DN;
    float4 a = *(const float4*)(np + lane * 4);
    float4 b = *(const float4*)(np + 128 + lane * 4);

    // mean
    float s = a.x + a.y + a.z + a.w + b.x + b.y + b.z + b.w;
    #pragma unroll
    for (int o = 16; o; o >>= 1) s += __shfl_xor_sync(0xffffffffu, s, o);
    float mu = s * (1.f / 256.f);

    // variance
    float dx0 = a.x - mu, dx1 = a.y - mu, dx2 = a.z - mu, dx3 = a.w - mu;
    float dy0 = b.x - mu, dy1 = b.y - mu, dy2 = b.z - mu, dy3 = b.w - mu;
    float q = dx0*dx0 + dx1*dx1 + dx2*dx2 + dx3*dx3
            + dy0*dy0 + dy1*dy1 + dy2*dy2 + dy3*dy3;
    #pragma unroll
    for (int o = 16; o; o >>= 1) q += __shfl_xor_sync(0xffffffffu, q, o);
    float rstd = rsqrtf(q * (1.f / 256.f) + LN_EPS);

    // normalized x -> smem (per-warp slab)
    float4 w0 = *(const float4*)(ln_w + lane * 4);
    float4 w1 = *(const float4*)(ln_w + 128 + lane * 4);
    float4 bb0 = *(const float4*)(ln_b + lane * 4);
    float4 bb1 = *(const float4*)(ln_b + 128 + lane * 4);
    float* xw = xs[warp];
    xw[lane*4+0] = dx0 * rstd * w0.x + bb0.x;
    xw[lane*4+1] = dx1 * rstd * w0.y + bb0.y;
    xw[lane*4+2] = dx2 * rstd * w0.z + bb0.z;
    xw[lane*4+3] = dx3 * rstd * w0.w + bb0.w;
    xw[128+lane*4+0] = dy0 * rstd * w1.x + bb1.x;
    xw[128+lane*4+1] = dy1 * rstd * w1.y + bb1.y;
    xw[128+lane*4+2] = dy2 * rstd * w1.z + bb1.z;
    xw[128+lane*4+3] = dy3 * rstd * w1.w + bb1.w;
    __syncwarp();

    // projections: lane computes left[lane] and right[lane]
    float accL = 0.f, accR = 0.f;
    #pragma unroll 8
    for (int k = 0; k < DN; k++) {
        float xv = xw[k];
        accL += xv * __ldg(wl + k * DH + lane);
        accR += xv * __ldg(wr + k * DH + lane);
    }
    g_left[n * DH + lane]  = accL + bl[lane];
    g_right[n * DH + lane] = accR + br[lane];
}

// ---------------- P2: T = left @ B, B = w_out viewed as [32][4096] ----------------
// grid (32 col-tiles x 16 n-tiles), 256 threads. Block computes T[32 n][128 col].
__global__ void p2_kernel(const float* __restrict__ w_out) {
    __shared__ float As[32 * 32];   // left slab [32 n][32 i]

    int nb = blockIdx.y * 32;
    int cb = blockIdx.x * 128;
    int tid = threadIdx.x;

    {
        int row = tid >> 3, qq = tid & 7;
        *(float4*)&As[row * 32 + qq * 4] =
            *(const float4*)(g_left + (nb + row) * DH + qq * 4);
    }
    __syncthreads();

    int col = cb + (tid & 127);
    int nset = tid >> 7;
    float acc[16];
    #pragma unroll
    for (int r = 0; r < 16; r++) acc[r] = 0.f;

    #pragma unroll 4
    for (int i = 0; i < 32; i++) {
        float b = w_out[i * 4096 + col];
        #pragma unroll
        for (int r = 0; r < 16; r++)
            acc[r] += As[(nset * 16 + r) * 32 + i] * b;
    }

    #pragma unroll
    for (int r = 0; r < 16; r++)
        g_T[(nb + nset * 16 + r) * (DH * DE) + col] = acc[r];
}

// ---------------- Main kernel: out = edge + b_out + right @ T ----------------
// Semi-persistent: 296 blocks (= 74 groups x 4 m-tiles). Each block owns one
// 128-m tile and a range of ~7 consecutive n. sR filled once; sT double-
// buffered via cp.async prefetch; edge LDGs issued under the cp.async wait.
__global__ void __launch_bounds__(256, 2)
outk_kernel(const float* __restrict__ edge,
            const float* __restrict__ b_out,
            float* __restrict__ out) {
    __shared__ __align__(16) float sR[DH * 128];        // transposed: [j][m_local]
    __shared__ __align__(16) float sT[2][DH * DE];      // [buf][j][e]

    int m_tile = blockIdx.x & 3;
    int grp    = blockIdx.x >> 2;                        // 0..73
    int n0 = (grp * NN) / NGROUPS;
    int n1 = ((grp + 1) * NN) / NGROUPS;
    int m_base = m_tile * 128;
    int tid = threadIdx.x;

    // fill sR transposed: sR[j][ml] = right[m_base+ml][j]  (once per block)
    {
        int ml = tid & 127;
        int jq0 = tid >> 7;
        #pragma unroll
        for (int it = 0; it < 4; it++) {
            int jq = jq0 + it * 2;
            float4 r4 = *(const float4*)(g_right + (m_base + ml) * DH + jq * 4);
            sR[(jq * 4 + 0) * 128 + ml] = r4.x;
            sR[(jq * 4 + 1) * 128 + ml] = r4.y;
            sR[(jq * 4 + 2) * 128 + ml] = r4.z;
            sR[(jq * 4 + 3) * 128 + ml] = r4.w;
        }
    }

    // prefetch T[n0] into buffer 0
    unsigned sT_base = (unsigned)__cvta_generic_to_shared(&sT[0][0]);
    {
        const char* g = (const char*)(g_T + (size_t)n0 * (DH * DE)) + tid * 16;
        #pragma unroll
        for (int k = 0; k < 4; k++)
            cp_async16(sT_base + tid * 16 + k * 4096, g + k * 4096);
        cp_commit();
    }

    int lane = tid & 31;
    int w    = tid >> 5;
    int e0 = lane * 4;
    int mt = w * 16;
    float4 b4 = *(const float4*)(b_out + e0);

    int ib = 0;
    for (int n = n0; n < n1; n++, ib ^= 1) {
        // prefetch next T while we work on this n
        if (n + 1 < n1) {
            const char* g = (const char*)(g_T + (size_t)(n + 1) * (DH * DE)) + tid * 16;
            unsigned sb = sT_base + (ib ^ 1) * (DH * DE * 4) + tid * 16;
            #pragma unroll
            for (int k = 0; k < 4; k++)
                cp_async16(sb + k * 4096, g + k * 4096);
            cp_commit();
        }

        // edge loads + acc init (LDGs resolve under the cp.async wait below)
        unsigned long long acc[8][4];
        const float* erow = edge + ((size_t)n * NN + m_base + mt) * DE + e0;
        #pragma unroll
        for (int mp = 0; mp < 8; mp++) {
            float4 ea = *(const float4*)(erow + (2 * mp) * DE);
            float4 eb = *(const float4*)(erow + (2 * mp + 1) * DE);
            acc[mp][0] = pk2(ea.x + b4.x, eb.x + b4.x);
            acc[mp][1] = pk2(ea.y + b4.y, eb.y + b4.y);
            acc[mp][2] = pk2(ea.z + b4.z, eb.z + b4.z);
            acc[mp][3] = pk2(ea.w + b4.w, eb.w + b4.w);
        }

        if (n + 1 < n1) cp_wait<1>(); else cp_wait<0>();
        __syncthreads();

        const float* sTb = &sT[ib][0];
        #pragma unroll 4
        for (int j = 0; j < DH; j++) {
            float4 t4 = *(const float4*)(sTb + j * DE + e0);
            unsigned long long t0 = pk2(t4.x, t4.x);
            unsigned long long t1 = pk2(t4.y, t4.y);
            unsigned long long t2 = pk2(t4.z, t4.z);
            unsigned long long t3 = pk2(t4.w, t4.w);
            const float* rj = sR + j * 128 + mt;
            #pragma unroll
            for (int mp = 0; mp < 8; mp++) {
                unsigned long long r2 = *(const unsigned long long*)(rj + 2 * mp);
                fma2(acc[mp][0], r2, t0);
                fma2(acc[mp][1], r2, t1);
                fma2(acc[mp][2], r2, t2);
                fma2(acc[mp][3], r2, t3);
            }
        }
        __syncthreads();   // protect sT[ib] before next iter's prefetch overwrites it

        // epilogue: pure STG.128 stream (fire-and-forget)
        float* orow = out + ((size_t)n * NN + m_base + mt) * DE + e0;
        #pragma unroll
        for (int mp = 0; mp < 8; mp++) {
            float a0, c0, a1, c1, a2, c2, a3, c3;
            upk2(acc[mp][0], a0, c0);
            upk2(acc[mp][1], a1, c1);
            upk2(acc[mp][2], a2, c2);
            upk2(acc[mp][3], a3, c3);
            *(float4*)(orow + (2 * mp) * DE)     = make_float4(a0, a1, a2, a3);
            *(float4*)(orow + (2 * mp + 1) * DE) = make_float4(c0, c1, c2, c3);
        }
    }
}

// ---------------- launch ----------------
extern "C" void kernel_launch(void* const* d_in, const int* in_sizes, int n_in,
                              void* d_out, int out_size) {
    const float* node   = (const float*)d_in[0];
    const float* edge   = (const float*)d_in[1];
    const float* ln_w   = (const float*)d_in[2];
    const float* ln_b   = (const float*)d_in[3];
    const float* w_left = (const float*)d_in[4];
    const float* b_left = (const float*)d_in[5];
    const float* w_right= (const float*)d_in[6];
    const float* b_right= (const float*)d_in[7];
    const float* w_out  = (const float*)d_in[8];
    const float* b_out  = (const float*)d_in[9];
    float* out = (float*)d_out;

    p1_kernel<<<128, 128>>>(node, ln_w, ln_b, w_left, b_left, w_right, b_right);
    p2_kernel<<<dim3(32, 16), 256>>>(w_out);
    outk_kernel<<<NGROUPS * 4, 256>>>(edge, b_out, out);
}

// round 3
// speedup vs baseline: 1.2838x; 1.2838x over previous
#include <cuda_runtime.h>

#define NN 512      // tokens
#define DN 256      // d_node
#define DE 128      // d_edge
#define DH 32       // d_head
#define LN_EPS 1e-5f

// Scratch (device globals: no allocation allowed)
__device__ float g_left[NN * DH];
__device__ float g_right[NN * DH];
__device__ float g_T[NN * DH * DE];   // [n][j][e] = [512][32][128]

// ---------------- packed f32x2 helpers (sm_103a) ----------------
__device__ __forceinline__ unsigned long long pk2(float lo, float hi) {
    unsigned long long r;
    asm("mov.b64 %0, {%1, %2};" : "=l"(r) : "f"(lo), "f"(hi));
    return r;
}
__device__ __forceinline__ void fma2(unsigned long long& d,
                                     unsigned long long a,
                                     unsigned long long b) {
    asm("fma.rn.f32x2 %0, %1, %2, %0;" : "+l"(d) : "l"(a), "l"(b));
}
__device__ __forceinline__ void upk2(unsigned long long v, float& lo, float& hi) {
    asm("mov.b64 {%0, %1}, %2;" : "=f"(lo), "=f"(hi) : "l"(v));
}

// ---------------- P1: LayerNorm + left/right projections ----------------
// One block per token (512 blocks x 256 threads). Single fused sum/sumsq
// reduction (var = E[x^2] - mu^2), 3 syncs total, 4-way ILP proj loop.
__global__ void p1_kernel(const float* __restrict__ node,
                          const float* __restrict__ ln_w,
                          const float* __restrict__ ln_b,
                          const float* __restrict__ wl,
                          const float* __restrict__ bl,
                          const float* __restrict__ wr,
                          const float* __restrict__ br) {
    __shared__ float xs[DN];
    __shared__ float2 red[8];
    __shared__ float ps[4][64];

    int n = blockIdx.x;
    int tid = threadIdx.x;

    float v = node[n * DN + tid];

    // fused sum + sumsq reduction
    float s = v, q = v * v;
    #pragma unroll
    for (int o = 16; o; o >>= 1) {
        s += __shfl_xor_sync(0xffffffffu, s, o);
        q += __shfl_xor_sync(0xffffffffu, q, o);
    }
    if ((tid & 31) == 0) red[tid >> 5] = make_float2(s, q);
    __syncthreads();
    float S = 0.f, Q = 0.f;
    #pragma unroll
    for (int i = 0; i < 8; i++) { S += red[i].x; Q += red[i].y; }
    float mu = S * (1.f / 256.f);
    float var = Q * (1.f / 256.f) - mu * mu;
    float rstd = rsqrtf(var + LN_EPS);

    xs[tid] = (v - mu) * rstd * ln_w[tid] + ln_b[tid];
    __syncthreads();

    // projections: thread t -> (h = t&31, sel = left/right, part = quarter of k)
    int h = tid & 31;
    int sel = (tid >> 5) & 1;
    int part = tid >> 6;
    const float* __restrict__ w = sel ? wr : wl;
    int k0 = part * 64;
    float a0 = 0.f, a1 = 0.f, a2 = 0.f, a3 = 0.f;
    #pragma unroll 4
    for (int k = 0; k < 64; k += 4) {
        a0 += xs[k0 + k + 0] * w[(k0 + k + 0) * DH + h];
        a1 += xs[k0 + k + 1] * w[(k0 + k + 1) * DH + h];
        a2 += xs[k0 + k + 2] * w[(k0 + k + 2) * DH + h];
        a3 += xs[k0 + k + 3] * w[(k0 + k + 3) * DH + h];
    }
    ps[part][sel * 32 + h] = (a0 + a1) + (a2 + a3);
    __syncthreads();

    if (tid < 64) {
        float r = ps[0][tid] + ps[1][tid] + ps[2][tid] + ps[3][tid];
        if (tid < 32) g_left[n * DH + tid] = r + bl[tid];
        else          g_right[n * DH + (tid - 32)] = r + br[tid - 32];
    }
}

// ---------------- P2: T = left @ B, B = w_out viewed as [32][4096] ----------------
__global__ void p2_kernel(const float* __restrict__ w_out) {
    __shared__ float As[32 * 32];   // left slab [32 n][32 i]

    int nb = blockIdx.y * 32;
    int cb = blockIdx.x * 128;
    int tid = threadIdx.x;

    {
        int row = tid >> 3, qq = tid & 7;
        *(float4*)&As[row * 32 + qq * 4] =
            *(const float4*)(g_left + (nb + row) * DH + qq * 4);
    }
    __syncthreads();

    int col = cb + (tid & 127);
    int nset = tid >> 7;
    float acc[16];
    #pragma unroll
    for (int r = 0; r < 16; r++) acc[r] = 0.f;

    #pragma unroll 4
    for (int i = 0; i < 32; i++) {
        float b = w_out[i * 4096 + col];
        #pragma unroll
        for (int r = 0; r < 16; r++)
            acc[r] += As[(nset * 16 + r) * 32 + i] * b;
    }

    #pragma unroll
    for (int r = 0; r < 16; r++)
        g_T[(nb + nset * 16 + r) * (DH * DE) + col] = acc[r];
}

// ---------------- Main kernel: out = edge + b_out + right @ T ----------------
// grid (4 m-tiles, 512 n), 512 threads, 2 blocks/SM (32 warps/SM).
// Per thread: 8 m x 4 e register tile as 16 packed f32x2 accumulators.
// edge via __ldcs / out via __stcs (pure streams) so T stays L2-resident.
__global__ void __launch_bounds__(512, 2)
outk_kernel(const float* __restrict__ edge,
            const float* __restrict__ b_out,
            float* __restrict__ out) {
    __shared__ __align__(16) float sT[DH * DE];   // [j][e]  = [32][128]
    __shared__ __align__(16) float sR[DH * 128];  // transposed: [j][m_local]

    int n = blockIdx.y;
    int m_base = blockIdx.x * 128;
    int tid = threadIdx.x;

    // fill sT: T[n] (16 KB), fully coalesced (1024 float4 / 512 threads)
    {
        const float4* gT4 = (const float4*)(g_T + (size_t)n * (DH * DE));
        float4* sT4 = (float4*)sT;
        sT4[tid]       = gT4[tid];
        sT4[tid + 512] = gT4[tid + 512];
    }
    // fill sR transposed: sR[j][ml] = right[m_base+ml][j]
    {
        int ml = tid & 127;
        int jq0 = tid >> 7;             // 0..3
        #pragma unroll
        for (int it = 0; it < 2; it++) {
            int jq = jq0 + it * 4;      // 0..7
            float4 r4 = *(const float4*)(g_right + (m_base + ml) * DH + jq * 4);
            sR[(jq * 4 + 0) * 128 + ml] = r4.x;
            sR[(jq * 4 + 1) * 128 + ml] = r4.y;
            sR[(jq * 4 + 2) * 128 + ml] = r4.z;
            sR[(jq * 4 + 3) * 128 + ml] = r4.w;
        }
    }

    int lane = tid & 31;
    int w    = tid >> 5;      // 16 warps
    int e0 = lane * 4;        // this thread's 4 e columns
    int mt = w * 8;           // this warp's 8 m rows (within tile)

    // init accumulators from edge + b_out (streaming loads; overlap smem fill)
    float4 b4 = *(const float4*)(b_out + e0);
    unsigned long long acc[4][4];
    const float4* erow = (const float4*)(edge + ((size_t)n * NN + m_base + mt) * DE + e0);
    #pragma unroll
    for (int mp = 0; mp < 4; mp++) {
        float4 ea = __ldcs(erow + (2 * mp) * (DE / 4));
        float4 eb = __ldcs(erow + (2 * mp + 1) * (DE / 4));
        acc[mp][0] = pk2(ea.x + b4.x, eb.x + b4.x);
        acc[mp][1] = pk2(ea.y + b4.y, eb.y + b4.y);
        acc[mp][2] = pk2(ea.z + b4.z, eb.z + b4.z);
        acc[mp][3] = pk2(ea.w + b4.w, eb.w + b4.w);
    }
    __syncthreads();

    // mainloop over j: 16 FFMA2 per thread per j (FMA-pipe bound)
    #pragma unroll 8
    for (int j = 0; j < DH; j++) {
        float4 t4 = *(const float4*)(sT + j * DE + e0);
        unsigned long long t0 = pk2(t4.x, t4.x);
        unsigned long long t1 = pk2(t4.y, t4.y);
        unsigned long long t2 = pk2(t4.z, t4.z);
        unsigned long long t3 = pk2(t4.w, t4.w);
        const float* rj = sR + j * 128 + mt;
        #pragma unroll
        for (int mp = 0; mp < 4; mp++) {
            unsigned long long r2 = *(const unsigned long long*)(rj + 2 * mp);
            fma2(acc[mp][0], r2, t0);
            fma2(acc[mp][1], r2, t1);
            fma2(acc[mp][2], r2, t2);
            fma2(acc[mp][3], r2, t3);
        }
    }

    // epilogue: streaming STG.128
    float4* orow = (float4*)(out + ((size_t)n * NN + m_base + mt) * DE + e0);
    #pragma unroll
    for (int mp = 0; mp < 4; mp++) {
        float a0, c0, a1, c1, a2, c2, a3, c3;
        upk2(acc[mp][0], a0, c0);
        upk2(acc[mp][1], a1, c1);
        upk2(acc[mp][2], a2, c2);
        upk2(acc[mp][3], a3, c3);
        __stcs(orow + (2 * mp) * (DE / 4),     make_float4(a0, a1, a2, a3));
        __stcs(orow + (2 * mp + 1) * (DE / 4), make_float4(c0, c1, c2, c3));
    }
}

// ---------------- launch ----------------
extern "C" void kernel_launch(void* const* d_in, const int* in_sizes, int n_in,
                              void* d_out, int out_size) {
    const float* node   = (const float*)d_in[0];
    const float* edge   = (const float*)d_in[1];
    const float* ln_w   = (const float*)d_in[2];
    const float* ln_b   = (const float*)d_in[3];
    const float* w_left = (const float*)d_in[4];
    const float* b_left = (const float*)d_in[5];
    const float* w_right= (const float*)d_in[6];
    const float* b_right= (const float*)d_in[7];
    const float* w_out  = (const float*)d_in[8];
    const float* b_out  = (const float*)d_in[9];
    float* out = (float*)d_out;

    p1_kernel<<<NN, 256>>>(node, ln_w, ln_b, w_left, b_left, w_right, b_right);
    p2_kernel<<<dim3(32, 16), 256>>>(w_out);
    outk_kernel<<<dim3(4, NN), 512>>>(edge, b_out, out);
}

// round 4
// speedup vs baseline: 1.4049x; 1.0943x over previous
#include <cuda_runtime.h>

#define NN 512      // tokens
#define DN 256      // d_node
#define DE 128      // d_edge
#define DH 32       // d_head
#define LN_EPS 1e-5f

// Scratch (device globals: no allocation allowed)
__device__ float g_left[NN * DH];
__device__ float g_right[NN * DH];
__device__ float g_T[NN * DH * DE];   // [n][j][e] = [512][32][128]

// ---------------- packed f32x2 helpers (sm_103a) ----------------
__device__ __forceinline__ unsigned long long pk2(float lo, float hi) {
    unsigned long long r;
    asm("mov.b64 %0, {%1, %2};" : "=l"(r) : "f"(lo), "f"(hi));
    return r;
}
__device__ __forceinline__ void fma2(unsigned long long& d,
                                     unsigned long long a,
                                     unsigned long long b) {
    asm("fma.rn.f32x2 %0, %1, %2, %0;" : "+l"(d) : "l"(a), "l"(b));
}
__device__ __forceinline__ void upk2(unsigned long long v, float& lo, float& hi) {
    asm("mov.b64 {%0, %1}, %2;" : "=f"(lo), "=f"(hi) : "l"(v));
}

// ---------------- P1: LayerNorm + left/right projections ----------------
// One block per token (512 blocks x 256 threads). Fused sum/sumsq reduction.
__global__ void p1_kernel(const float* __restrict__ node,
                          const float* __restrict__ ln_w,
                          const float* __restrict__ ln_b,
                          const float* __restrict__ wl,
                          const float* __restrict__ bl,
                          const float* __restrict__ wr,
                          const float* __restrict__ br) {
    __shared__ float xs[DN];
    __shared__ float2 red[8];
    __shared__ float ps[4][64];

    int n = blockIdx.x;
    int tid = threadIdx.x;

    float v = node[n * DN + tid];

    // fused sum + sumsq reduction
    float s = v, q = v * v;
    #pragma unroll
    for (int o = 16; o; o >>= 1) {
        s += __shfl_xor_sync(0xffffffffu, s, o);
        q += __shfl_xor_sync(0xffffffffu, q, o);
    }
    if ((tid & 31) == 0) red[tid >> 5] = make_float2(s, q);
    __syncthreads();
    float S = 0.f, Q = 0.f;
    #pragma unroll
    for (int i = 0; i < 8; i++) { S += red[i].x; Q += red[i].y; }
    float mu = S * (1.f / 256.f);
    float var = Q * (1.f / 256.f) - mu * mu;
    float rstd = rsqrtf(var + LN_EPS);

    xs[tid] = (v - mu) * rstd * ln_w[tid] + ln_b[tid];
    __syncthreads();

    // projections: thread t -> (h = t&31, sel = left/right, part = quarter of k)
    int h = tid & 31;
    int sel = (tid >> 5) & 1;
    int part = tid >> 6;
    const float* __restrict__ w = sel ? wr : wl;
    int k0 = part * 64;
    float a0 = 0.f, a1 = 0.f, a2 = 0.f, a3 = 0.f;
    #pragma unroll 4
    for (int k = 0; k < 64; k += 4) {
        a0 += xs[k0 + k + 0] * w[(k0 + k + 0) * DH + h];
        a1 += xs[k0 + k + 1] * w[(k0 + k + 1) * DH + h];
        a2 += xs[k0 + k + 2] * w[(k0 + k + 2) * DH + h];
        a3 += xs[k0 + k + 3] * w[(k0 + k + 3) * DH + h];
    }
    ps[part][sel * 32 + h] = (a0 + a1) + (a2 + a3);
    __syncthreads();

    if (tid < 64) {
        float r = ps[0][tid] + ps[1][tid] + ps[2][tid] + ps[3][tid];
        if (tid < 32) g_left[n * DH + tid] = r + bl[tid];
        else          g_right[n * DH + (tid - 32)] = r + br[tid - 32];
    }
}

// ---------------- P2: T = left @ B, B = w_out viewed as [32][4096] ----------------
__global__ void p2_kernel(const float* __restrict__ w_out) {
    __shared__ float As[32 * 32];   // left slab [32 n][32 i]

    int nb = blockIdx.y * 32;
    int cb = blockIdx.x * 128;
    int tid = threadIdx.x;

    {
        int row = tid >> 3, qq = tid & 7;
        *(float4*)&As[row * 32 + qq * 4] =
            *(const float4*)(g_left + (nb + row) * DH + qq * 4);
    }
    __syncthreads();

    int col = cb + (tid & 127);
    int nset = tid >> 7;
    float acc[16];
    #pragma unroll
    for (int r = 0; r < 16; r++) acc[r] = 0.f;

    #pragma unroll 4
    for (int i = 0; i < 32; i++) {
        float b = w_out[i * 4096 + col];
        #pragma unroll
        for (int r = 0; r < 16; r++)
            acc[r] += As[(nset * 16 + r) * 32 + i] * b;
    }

    #pragma unroll
    for (int r = 0; r < 16; r++)
        g_T[(nb + nset * 16 + r) * (DH * DE) + col] = acc[r];
}

// ---------------- Main kernel: out = edge + b_out + right @ T ----------------
// grid (4 m-tiles, 512 n), 256 threads, 2 blocks/SM. Per thread: 16m x 4e tile
// as 32 packed f32x2 accumulators. Edge LDGs issued FIRST (streaming, __ldcs),
// consumed only after the smem fill + barrier -> latency fully hidden.
__global__ void __launch_bounds__(256, 2)
outk_kernel(const float* __restrict__ edge,
            const float* __restrict__ b_out,
            float* __restrict__ out) {
    __shared__ __align__(16) float sT[DH * DE];   // [j][e]  = [32][128]
    __shared__ __align__(16) float sR[DH * 128];  // transposed: [j][m_local]

    int n = blockIdx.y;
    int m_base = blockIdx.x * 128;
    int tid = threadIdx.x;
    int lane = tid & 31;
    int w    = tid >> 5;
    int e0 = lane * 4;        // this thread's 4 e columns
    int mt = w * 16;          // this warp's 16 m rows (within tile)

    // 1) issue ALL edge loads first (streaming; evict-first keeps T in L2)
    const float4* erow = (const float4*)(edge + ((size_t)n * NN + m_base + mt) * DE + e0);
    float4 ev[16];
    #pragma unroll
    for (int r = 0; r < 16; r++) ev[r] = __ldcs(erow + r * (DE / 4));

    // 2) smem fills (their latency + barrier hide the edge loads)
    {
        const float4* gT4 = (const float4*)(g_T + (size_t)n * (DH * DE));
        float4* sT4 = (float4*)sT;
        #pragma unroll
        for (int k = 0; k < 4; k++) sT4[tid + k * 256] = gT4[tid + k * 256];
    }
    {
        int ml = tid & 127;
        int jq0 = tid >> 7;
        #pragma unroll
        for (int it = 0; it < 4; it++) {
            int jq = jq0 + it * 2;
            float4 r4 = *(const float4*)(g_right + (m_base + ml) * DH + jq * 4);
            sR[(jq * 4 + 0) * 128 + ml] = r4.x;
            sR[(jq * 4 + 1) * 128 + ml] = r4.y;
            sR[(jq * 4 + 2) * 128 + ml] = r4.z;
            sR[(jq * 4 + 3) * 128 + ml] = r4.w;
        }
    }
    __syncthreads();

    // 3) accumulator init from (already-arrived) edge + b_out
    float4 b4 = *(const float4*)(b_out + e0);
    unsigned long long acc[8][4];
    #pragma unroll
    for (int mp = 0; mp < 8; mp++) {
        float4 ea = ev[2 * mp];
        float4 eb = ev[2 * mp + 1];
        acc[mp][0] = pk2(ea.x + b4.x, eb.x + b4.x);
        acc[mp][1] = pk2(ea.y + b4.y, eb.y + b4.y);
        acc[mp][2] = pk2(ea.z + b4.z, eb.z + b4.z);
        acc[mp][3] = pk2(ea.w + b4.w, eb.w + b4.w);
    }

    // 4) mainloop over j: 32 FFMA2 per thread per j (FMA-pipe bound)
    #pragma unroll 8
    for (int j = 0; j < DH; j++) {
        float4 t4 = *(const float4*)(sT + j * DE + e0);
        unsigned long long t0 = pk2(t4.x, t4.x);
        unsigned long long t1 = pk2(t4.y, t4.y);
        unsigned long long t2 = pk2(t4.z, t4.z);
        unsigned long long t3 = pk2(t4.w, t4.w);
        const float* rj = sR + j * 128 + mt;
        #pragma unroll
        for (int mp = 0; mp < 8; mp++) {
            unsigned long long r2 = *(const unsigned long long*)(rj + 2 * mp);
            fma2(acc[mp][0], r2, t0);
            fma2(acc[mp][1], r2, t1);
            fma2(acc[mp][2], r2, t2);
            fma2(acc[mp][3], r2, t3);
        }
    }

    // 5) epilogue: pure STG.128 stream
    float* orow = out + ((size_t)n * NN + m_base + mt) * DE + e0;
    #pragma unroll
    for (int mp = 0; mp < 8; mp++) {
        float a0, c0, a1, c1, a2, c2, a3, c3;
        upk2(acc[mp][0], a0, c0);
        upk2(acc[mp][1], a1, c1);
        upk2(acc[mp][2], a2, c2);
        upk2(acc[mp][3], a3, c3);
        *(float4*)(orow + (2 * mp) * DE)     = make_float4(a0, a1, a2, a3);
        *(float4*)(orow + (2 * mp + 1) * DE) = make_float4(c0, c1, c2, c3);
    }
}

// ---------------- launch ----------------
extern "C" void kernel_launch(void* const* d_in, const int* in_sizes, int n_in,
                              void* d_out, int out_size) {
    const float* node   = (const float*)d_in[0];
    const float* edge   = (const float*)d_in[1];
    const float* ln_w   = (const float*)d_in[2];
    const float* ln_b   = (const float*)d_in[3];
    const float* w_left = (const float*)d_in[4];
    const float* b_left = (const float*)d_in[5];
    const float* w_right= (const float*)d_in[6];
    const float* b_right= (const float*)d_in[7];
    const float* w_out  = (const float*)d_in[8];
    const float* b_out  = (const float*)d_in[9];
    float* out = (float*)d_out;

    p1_kernel<<<NN, 256>>>(node, ln_w, ln_b, w_left, b_left, w_right, b_right);
    p2_kernel<<<dim3(32, 16), 256>>>(w_out);
    outk_kernel<<<dim3(4, NN), 256>>>(edge, b_out, out);
}

// round 5
// speedup vs baseline: 1.4066x; 1.0013x over previous
#include <cuda_runtime.h>

#define NN 512      // tokens
#define DN 256      // d_node
#define DE 128      // d_edge
#define DH 32       // d_head
#define LN_EPS 1e-5f
#define NGRP 37     // outk n-groups (37 * 4 m-tiles = 148 blocks = 1 per SM)

// Scratch (device globals: no allocation allowed)
__device__ float g_left[NN * DH];
__device__ float g_right[NN * DH];
__device__ float g_T[NN * DH * DE];   // [n][j][e] = [512][32][128]

// ---------------- packed f32x2 helpers (sm_103a) ----------------
__device__ __forceinline__ unsigned long long pk2(float lo, float hi) {
    unsigned long long r;
    asm("mov.b64 %0, {%1, %2};" : "=l"(r) : "f"(lo), "f"(hi));
    return r;
}
__device__ __forceinline__ void fma2(unsigned long long& d,
                                     unsigned long long a,
                                     unsigned long long b) {
    asm("fma.rn.f32x2 %0, %1, %2, %0;" : "+l"(d) : "l"(a), "l"(b));
}
__device__ __forceinline__ void upk2(unsigned long long v, float& lo, float& hi) {
    asm("mov.b64 {%0, %1}, %2;" : "=f"(lo), "=f"(hi) : "l"(v));
}

// ---------------- cp.async helpers ----------------
__device__ __forceinline__ void cp_async16(unsigned smem_addr, const void* gptr) {
    asm volatile("cp.async.cg.shared.global [%0], [%1], 16;"
                 :: "r"(smem_addr), "l"(gptr));
}
__device__ __forceinline__ void cp_commit() {
    asm volatile("cp.async.commit_group;");
}
__device__ __forceinline__ void cp_wait_all() {
    asm volatile("cp.async.wait_group 0;");
}

// ---------------- P1: LayerNorm + left/right projections ----------------
__global__ void p1_kernel(const float* __restrict__ node,
                          const float* __restrict__ ln_w,
                          const float* __restrict__ ln_b,
                          const float* __restrict__ wl,
                          const float* __restrict__ bl,
                          const float* __restrict__ wr,
                          const float* __restrict__ br) {
    __shared__ float xs[DN];
    __shared__ float2 red[8];
    __shared__ float ps[4][64];

    int n = blockIdx.x;
    int tid = threadIdx.x;

    float v = node[n * DN + tid];

    float s = v, q = v * v;
    #pragma unroll
    for (int o = 16; o; o >>= 1) {
        s += __shfl_xor_sync(0xffffffffu, s, o);
        q += __shfl_xor_sync(0xffffffffu, q, o);
    }
    if ((tid & 31) == 0) red[tid >> 5] = make_float2(s, q);
    __syncthreads();
    float S = 0.f, Q = 0.f;
    #pragma unroll
    for (int i = 0; i < 8; i++) { S += red[i].x; Q += red[i].y; }
    float mu = S * (1.f / 256.f);
    float var = Q * (1.f / 256.f) - mu * mu;
    float rstd = rsqrtf(var + LN_EPS);

    xs[tid] = (v - mu) * rstd * ln_w[tid] + ln_b[tid];
    __syncthreads();

    int h = tid & 31;
    int sel = (tid >> 5) & 1;
    int part = tid >> 6;
    const float* __restrict__ w = sel ? wr : wl;
    int k0 = part * 64;
    float a0 = 0.f, a1 = 0.f, a2 = 0.f, a3 = 0.f;
    #pragma unroll 4
    for (int k = 0; k < 64; k += 4) {
        a0 += xs[k0 + k + 0] * w[(k0 + k + 0) * DH + h];
        a1 += xs[k0 + k + 1] * w[(k0 + k + 1) * DH + h];
        a2 += xs[k0 + k + 2] * w[(k0 + k + 2) * DH + h];
        a3 += xs[k0 + k + 3] * w[(k0 + k + 3) * DH + h];
    }
    ps[part][sel * 32 + h] = (a0 + a1) + (a2 + a3);
    __syncthreads();

    if (tid < 64) {
        float r = ps[0][tid] + ps[1][tid] + ps[2][tid] + ps[3][tid];
        if (tid < 32) g_left[n * DH + tid] = r + bl[tid];
        else          g_right[n * DH + (tid - 32)] = r + br[tid - 32];
    }
}

// ---------------- P2: T = left @ B, B = w_out viewed as [32][4096] ----------------
__global__ void p2_kernel(const float* __restrict__ w_out) {
    __shared__ float As[32 * 32];

    int nb = blockIdx.y * 32;
    int cb = blockIdx.x * 128;
    int tid = threadIdx.x;

    {
        int row = tid >> 3, qq = tid & 7;
        *(float4*)&As[row * 32 + qq * 4] =
            *(const float4*)(g_left + (nb + row) * DH + qq * 4);
    }
    __syncthreads();

    int col = cb + (tid & 127);
    int nset = tid >> 7;
    float acc[16];
    #pragma unroll
    for (int r = 0; r < 16; r++) acc[r] = 0.f;

    #pragma unroll 4
    for (int i = 0; i < 32; i++) {
        float b = w_out[i * 4096 + col];
        #pragma unroll
        for (int r = 0; r < 16; r++)
            acc[r] += As[(nset * 16 + r) * 32 + i] * b;
    }

    #pragma unroll
    for (int r = 0; r < 16; r++)
        g_T[(nb + nset * 16 + r) * (DH * DE) + col] = acc[r];
}

// ---------------- Main kernel: out = edge + b_out + right @ T ----------------
// Persistent: 148 blocks (1/SM) x 512 threads. Block = (m-tile fixed, ~14 n).
// sR once; sT double-buffered cp.async; edge prefetched into regs one item
// ahead -> memory stream runs continuously under the fma loop.
__global__ void __launch_bounds__(512, 1)
outk_kernel(const float* __restrict__ edge,
            const float* __restrict__ b_out,
            float* __restrict__ out) {
    __shared__ __align__(16) float sR[DH * 128];      // transposed: [j][m_local]
    __shared__ __align__(16) float sT[2][DH * DE];    // [buf][j][e]

    int m_tile = blockIdx.x & 3;
    int grp    = blockIdx.x >> 2;                     // 0..36
    int n0 = (grp * NN) / NGRP;
    int n1 = ((grp + 1) * NN) / NGRP;
    int m_base = m_tile * 128;
    int tid = threadIdx.x;
    int lane = tid & 31;
    int w    = tid >> 5;          // 0..15
    int e0 = lane * 4;            // 4 e columns per thread
    int mt = w * 8;               // 8 m rows per warp

    unsigned sT_base = (unsigned)__cvta_generic_to_shared(&sT[0][0]);

    // preload sT[n0] into buf 0 (16 KB: 2 x 16B per thread)
    {
        const char* g = (const char*)(g_T + (size_t)n0 * (DH * DE)) + tid * 16;
        cp_async16(sT_base + tid * 16, g);
        cp_async16(sT_base + tid * 16 + 8192, g + 8192);
        cp_commit();
    }

    // preload edge[n0] into registers (streaming)
    float4 ev[8];
    {
        const float4* erow = (const float4*)(edge + ((size_t)n0 * NN + m_base + mt) * DE + e0);
        #pragma unroll
        for (int r = 0; r < 8; r++) ev[r] = __ldcs(erow + r * (DE / 4));
    }

    // fill sR (once): sR[j][ml] = right[m_base+ml][j]
    {
        int ml = tid & 127;
        #pragma unroll
        for (int it = 0; it < 2; it++) {
            int jq = (tid >> 7) + it * 4;      // 0..7
            float4 r4 = *(const float4*)(g_right + (m_base + ml) * DH + jq * 4);
            sR[(jq * 4 + 0) * 128 + ml] = r4.x;
            sR[(jq * 4 + 1) * 128 + ml] = r4.y;
            sR[(jq * 4 + 2) * 128 + ml] = r4.z;
            sR[(jq * 4 + 3) * 128 + ml] = r4.w;
        }
    }

    float4 b4 = *(const float4*)(b_out + e0);

    cp_wait_all();
    __syncthreads();

    int buf = 0;
    for (int n = n0; n < n1; n++, buf ^= 1) {
        bool more = (n + 1 < n1);

        // prefetch sT[n+1] into other buffer (in flight during fma loop)
        if (more) {
            const char* g = (const char*)(g_T + (size_t)(n + 1) * (DH * DE)) + tid * 16;
            unsigned sb = sT_base + (buf ^ 1) * (DH * DE * 4) + tid * 16;
            cp_async16(sb, g);
            cp_async16(sb + 8192, g + 8192);
            cp_commit();
        }

        // accumulator init from prefetched edge + b_out
        unsigned long long acc[4][4];
        #pragma unroll
        for (int mp = 0; mp < 4; mp++) {
            float4 ea = ev[2 * mp];
            float4 eb = ev[2 * mp + 1];
            acc[mp][0] = pk2(ea.x + b4.x, eb.x + b4.x);
            acc[mp][1] = pk2(ea.y + b4.y, eb.y + b4.y);
            acc[mp][2] = pk2(ea.z + b4.z, eb.z + b4.z);
            acc[mp][3] = pk2(ea.w + b4.w, eb.w + b4.w);
        }

        // prefetch edge[n+1] into ev (LDGs overlap the fma loop below)
        if (more) {
            const float4* erow = (const float4*)(edge + ((size_t)(n + 1) * NN + m_base + mt) * DE + e0);
            #pragma unroll
            for (int r = 0; r < 8; r++) ev[r] = __ldcs(erow + r * (DE / 4));
        }

        // fma mainloop: 16 FFMA2 + 3 LDS.128 per thread per j
        const float* sTb = &sT[buf][0];
        #pragma unroll 8
        for (int j = 0; j < DH; j++) {
            float4 t4 = *(const float4*)(sTb + j * DE + e0);
            unsigned long long t0 = pk2(t4.x, t4.x);
            unsigned long long t1 = pk2(t4.y, t4.y);
            unsigned long long t2 = pk2(t4.z, t4.z);
            unsigned long long t3 = pk2(t4.w, t4.w);
            const ulonglong2* rj = (const ulonglong2*)(sR + j * 128 + mt);
            ulonglong2 rA = rj[0];   // m-pairs (0,1),(2,3)
            ulonglong2 rB = rj[1];   // m-pairs (4,5),(6,7)
            fma2(acc[0][0], rA.x, t0); fma2(acc[0][1], rA.x, t1);
            fma2(acc[0][2], rA.x, t2); fma2(acc[0][3], rA.x, t3);
            fma2(acc[1][0], rA.y, t0); fma2(acc[1][1], rA.y, t1);
            fma2(acc[1][2], rA.y, t2); fma2(acc[1][3], rA.y, t3);
            fma2(acc[2][0], rB.x, t0); fma2(acc[2][1], rB.x, t1);
            fma2(acc[2][2], rB.x, t2); fma2(acc[2][3], rB.x, t3);
            fma2(acc[3][0], rB.y, t0); fma2(acc[3][1], rB.y, t1);
            fma2(acc[3][2], rB.y, t2); fma2(acc[3][3], rB.y, t3);
        }

        // epilogue: streaming STG.128
        float* orow = out + ((size_t)n * NN + m_base + mt) * DE + e0;
        #pragma unroll
        for (int mp = 0; mp < 4; mp++) {
            float a0, c0, a1, c1, a2, c2, a3, c3;
            upk2(acc[mp][0], a0, c0);
            upk2(acc[mp][1], a1, c1);
            upk2(acc[mp][2], a2, c2);
            upk2(acc[mp][3], a3, c3);
            __stcs((float4*)(orow + (2 * mp) * DE),     make_float4(a0, a1, a2, a3));
            __stcs((float4*)(orow + (2 * mp + 1) * DE), make_float4(c0, c1, c2, c3));
        }

        if (more) {
            cp_wait_all();
            __syncthreads();
        }
    }
}

// ---------------- launch ----------------
extern "C" void kernel_launch(void* const* d_in, const int* in_sizes, int n_in,
                              void* d_out, int out_size) {
    const float* node   = (const float*)d_in[0];
    const float* edge   = (const float*)d_in[1];
    const float* ln_w   = (const float*)d_in[2];
    const float* ln_b   = (const float*)d_in[3];
    const float* w_left = (const float*)d_in[4];
    const float* b_left = (const float*)d_in[5];
    const float* w_right= (const float*)d_in[6];
    const float* b_right= (const float*)d_in[7];
    const float* w_out  = (const float*)d_in[8];
    const float* b_out  = (const float*)d_in[9];
    float* out = (float*)d_out;

    p1_kernel<<<NN, 256>>>(node, ln_w, ln_b, w_left, b_left, w_right, b_right);
    p2_kernel<<<dim3(32, 16), 256>>>(w_out);
    outk_kernel<<<NGRP * 4, 512>>>(edge, b_out, out);
}